// round 15
// baseline (speedup 1.0000x reference)
#include <cuda_runtime.h>
#include <cuda_bf16.h>
#include <math.h>
#include <cstdint>

// ---------------- problem constants ----------------
#define NN 10000      // nodes
#define NE 80000      // edges
#define NG 64         // graphs
#define HH 4          // heads
#define DD 512        // per-head dim
#define HD 2048       // H*D
#define EMB 768
#define HF  512
#define SLOPE 0.2f

// ---------------- scratch (device globals, allocation-free) ----------------
__device__ __align__(128) float g_feat[(size_t)NN * HD];   // GAT fc output (fp32)
__device__ __align__(128) float g_h0  [(size_t)NN * HF];   // final hidden (fp32)
__device__ __align__(128) float g_e   [NE * HH];           // edge logits -> exp values
__device__ float g_el[NN * HH], g_er[NN * HH];
__device__ float g_emax[NN * HH], g_den[NN * HH];
__device__ int   g_indeg[NN], g_cursor[NN], g_off[NN + 1], g_csr[NE];
__device__ int   g_gstart[NG], g_gend[NG];
__device__ float g_hg[NG * HF], g_hg2[NG * HF];

// bf16 hi/lo pairs: activations (2 ping-pong pairs) + weight arena
#define WARENA 9000000
__device__ __align__(128) __nv_bfloat16 g_ah[(size_t)NN * HD];
__device__ __align__(128) __nv_bfloat16 g_al[(size_t)NN * HD];
__device__ __align__(128) __nv_bfloat16 g_bh[(size_t)NN * HD];
__device__ __align__(128) __nv_bfloat16 g_bl[(size_t)NN * HD];
__device__ __align__(128) __nv_bfloat16 g_wth[WARENA];
__device__ __align__(128) __nv_bfloat16 g_wtl[WARENA];

// weight arena offsets (elements; [N,K] row-major per weight)
#define OFF_W1   0
#define OFF_W2   (OFF_W1 + 2048 * 768)
#define OFF_WFC  (OFF_W2 + 2048 * 2048)
#define OFF_WH   (OFF_WFC + 512 * 2048)
#define WH_SZ    (512 * 512)

// ---------------- small PTX helpers (sm_80+ features only) ----------------
__device__ __forceinline__ uint32_t smem_u32(const void* p) {
    uint32_t a;
    asm("{ .reg .u64 t; cvta.to.shared.u64 t, %1; cvt.u32.u64 %0, t; }"
        : "=r"(a) : "l"(p));
    return a;
}

__device__ __forceinline__ void cp_async16(uint32_t saddr, const void* gaddr) {
    asm volatile("cp.async.cg.shared.global [%0], [%1], 16;"
                 :: "r"(saddr), "l"(gaddr));
}
#define CP_COMMIT()  asm volatile("cp.async.commit_group;" ::: "memory")
#define CP_WAIT(n)   asm volatile("cp.async.wait_group %0;" :: "n"(n) : "memory")

__device__ __forceinline__ void ldmx4(uint32_t* f, uint32_t saddr) {
    asm volatile("ldmatrix.sync.aligned.m8n8.x4.shared.b16 {%0,%1,%2,%3}, [%4];"
                 : "=r"(f[0]), "=r"(f[1]), "=r"(f[2]), "=r"(f[3]) : "r"(saddr));
}

__device__ __forceinline__ void mma16816(float* c, const uint32_t* a, const uint32_t* b) {
    asm volatile(
        "mma.sync.aligned.m16n8k16.row.col.f32.bf16.bf16.f32 "
        "{%0,%1,%2,%3}, {%4,%5,%6,%7}, {%8,%9}, {%0,%1,%2,%3};"
        : "+f"(c[0]), "+f"(c[1]), "+f"(c[2]), "+f"(c[3])
        : "r"(a[0]), "r"(a[1]), "r"(a[2]), "r"(a[3]), "r"(b[0]), "r"(b[1]));
}

__device__ __forceinline__ void split_bf16(float v, __nv_bfloat16& h, __nv_bfloat16& l) {
    h = __float2bfloat16(v);
    l = __float2bfloat16(v - __bfloat162float(h));
}

// ---------------- tensor-core GEMM via mma.sync (HMMA, bf16x3) ----------------
// C[M,N] = act(A[M,K] @ Bt[N,K]^T + bias),  A/Bt given as bf16 hi/lo pairs.
// 256x128 tile/CTA, BK=32, cp.async double-buffered, ONE barrier per chunk.
// 8 warps (4m x 2n), each warp 64x64 via m16n8k16 -> 85B smem reads per MMA
// (vs 128B at 32x64), breaking the smem-BW / tensor-pipe co-saturation.
// Pass-major schedule: same-acc reuse distance = 16 MMAs.
#define TS      40                       // smem row stride (bf16 elems), 80B
#define TILE_A  (256 * TS)               // A operand tile (elems)
#define TILE_B  (128 * TS)               // B operand tile (elems)
#define BUF_E   (2 * TILE_A + 2 * TILE_B)
#define TC_SMEM (2 * BUF_E * 2)          // bytes (two buffers) = 122880

__global__ __launch_bounds__(256, 1)
void tc_gemm(const __nv_bfloat16* __restrict__ Ah, const __nv_bfloat16* __restrict__ Al,
             const __nv_bfloat16* __restrict__ Bh, const __nv_bfloat16* __restrict__ Bl,
             const float* __restrict__ bias, float* __restrict__ C,
             __nv_bfloat16* __restrict__ Chi, __nv_bfloat16* __restrict__ Clo,
             int M, int N, int K, int act)
{
    extern __shared__ __nv_bfloat16 smem[];
    const uint32_t sb = smem_u32(smem);
    const int tid = threadIdx.x;
    const int lane = tid & 31;
    const int wid = tid >> 5;
    const int wm = wid >> 1, wn = wid & 1;
    const int m0 = wm * 64, n0 = wn * 64;
    const int bm = blockIdx.y * 256;
    const int bn = blockIdx.x * 128;
    const int NC = K >> 5;

    // ---- cp.async load of one K-chunk into buffer b ----
    auto load_chunk = [&](int c, int b) {
        const int k0 = c << 5;
        const uint32_t base = sb + (uint32_t)b * BUF_E * 2;
        // A region: 2 tiles x 256 rows x 4 16B-chunks = 2048 chunks
        #pragma unroll
        for (int i = 0; i < 8; i++) {
            const int ci = i * 256 + tid;
            const int tile = ci >> 10;               // 0:Ah 1:Al
            const int row = (ci >> 2) & 255;
            const int c4 = ci & 3;
            const uint32_t sa = base + (uint32_t)(tile * TILE_A + row * TS + c4 * 8) * 2;
            int gr = bm + row; if (gr >= M) gr = M - 1;
            const __nv_bfloat16* src = (tile ? Al : Ah) + (size_t)gr * K + k0 + c4 * 8;
            cp_async16(sa, src);
        }
        // B region: 2 tiles x 128 rows x 4 chunks = 1024 chunks
        #pragma unroll
        for (int i = 0; i < 4; i++) {
            const int ci = i * 256 + tid;
            const int tile = ci >> 9;                // 0:Bh 1:Bl
            const int row = (ci >> 2) & 127;
            const int c4 = ci & 3;
            const uint32_t sa = base +
                (uint32_t)(2 * TILE_A + tile * TILE_B + row * TS + c4 * 8) * 2;
            const __nv_bfloat16* src = (tile ? Bl : Bh) + (size_t)(bn + row) * K + k0 + c4 * 8;
            cp_async16(sa, src);
        }
        CP_COMMIT();
    };

    float acc[4][8][4];
    #pragma unroll
    for (int mt = 0; mt < 4; mt++)
        #pragma unroll
        for (int nt = 0; nt < 8; nt++)
            #pragma unroll
            for (int q = 0; q < 4; q++) acc[mt][nt][q] = 0.f;

    load_chunk(0, 0);

    for (int c = 0; c < NC; c++) {
        const int b = c & 1;
        // wait for chunk c (only outstanding group), then ONE barrier.
        CP_WAIT(0);
        __syncthreads();
        // Safe to overwrite buffer 1-b: its readers finished in iteration
        // c-1, and every thread passed the barrier above since then.
        if (c + 1 < NC) load_chunk(c + 1, 1 - b);

        const uint32_t bufb = sb + (uint32_t)b * BUF_E * 2;
        const uint32_t sAh = bufb;
        const uint32_t sAl = bufb + TILE_A * 2;
        const uint32_t sBh = bufb + 2 * TILE_A * 2;
        const uint32_t sBl = bufb + (2 * TILE_A + TILE_B) * 2;

        #pragma unroll
        for (int ks = 0; ks < 2; ks++) {
            const int kk = ks * 16;
            uint32_t ahf[4][4], alf[4][4];
            const uint32_t aoff =
                (uint32_t)((m0 + (lane & 15)) * TS + kk + (lane >> 4) * 8) * 2;
            #pragma unroll
            for (int mt = 0; mt < 4; mt++) {
                ldmx4(ahf[mt], sAh + aoff + (uint32_t)(mt * 16 * TS) * 2);
                ldmx4(alf[mt], sAl + aoff + (uint32_t)(mt * 16 * TS) * 2);
            }
            const uint32_t boff =
                (uint32_t)((n0 + (lane & 7) + ((lane & 16) ? 8 : 0)) * TS
                           + kk + ((lane & 8) ? 8 : 0)) * 2;
            // n-tiles in pairs; within a pair issue pass-major:
            // each pass touches 16 distinct accumulators (4mt x 2x2nt).
            #pragma unroll
            for (int nph = 0; nph < 2; nph++) {
                uint32_t bhf[2][4], blf[2][4];
                #pragma unroll
                for (int p = 0; p < 2; p++) {
                    const uint32_t o =
                        boff + (uint32_t)((nph * 2 + p) * 16 * TS) * 2;
                    ldmx4(bhf[p], sBh + o);
                    ldmx4(blf[p], sBl + o);
                }
                // pass 1: Ah * Bh
                #pragma unroll
                for (int p = 0; p < 2; p++) {
                    const int nt = (nph * 2 + p) * 2;
                    #pragma unroll
                    for (int mt = 0; mt < 4; mt++) {
                        mma16816(acc[mt][nt],     ahf[mt], bhf[p]);
                        mma16816(acc[mt][nt + 1], ahf[mt], bhf[p] + 2);
                    }
                }
                // pass 2: Ah * Bl
                #pragma unroll
                for (int p = 0; p < 2; p++) {
                    const int nt = (nph * 2 + p) * 2;
                    #pragma unroll
                    for (int mt = 0; mt < 4; mt++) {
                        mma16816(acc[mt][nt],     ahf[mt], blf[p]);
                        mma16816(acc[mt][nt + 1], ahf[mt], blf[p] + 2);
                    }
                }
                // pass 3: Al * Bh
                #pragma unroll
                for (int p = 0; p < 2; p++) {
                    const int nt = (nph * 2 + p) * 2;
                    #pragma unroll
                    for (int mt = 0; mt < 4; mt++) {
                        mma16816(acc[mt][nt],     alf[mt], bhf[p]);
                        mma16816(acc[mt][nt + 1], alf[mt], bhf[p] + 2);
                    }
                }
            }
        }
    }

    // ---- epilogue ----
    #pragma unroll
    for (int mt = 0; mt < 4; mt++) {
        #pragma unroll
        for (int half = 0; half < 2; half++) {
            const int grow = bm + m0 + mt * 16 + (lane >> 2) + half * 8;
            if (grow >= M) continue;
            #pragma unroll
            for (int nt = 0; nt < 8; nt++) {
                const int gcol = bn + n0 + nt * 8 + (lane & 3) * 2;
                float v0 = acc[mt][nt][half * 2 + 0];
                float v1 = acc[mt][nt][half * 2 + 1];
                if (bias) { v0 += bias[gcol]; v1 += bias[gcol + 1]; }
                if (act) {
                    v0 = v0 > 0.f ? v0 : expm1f(v0);
                    v1 = v1 > 0.f ? v1 : expm1f(v1);
                }
                const size_t idx = (size_t)grow * N + gcol;
                if (C) *(float2*)(C + idx) = make_float2(v0, v1);
                if (Chi) {
                    __nv_bfloat16 h0, l0, h1, l1;
                    split_bf16(v0, h0, l0);
                    split_bf16(v1, h1, l1);
                    *(__nv_bfloat162*)(Chi + idx) = __nv_bfloat162(h0, h1);
                    *(__nv_bfloat162*)(Clo + idx) = __nv_bfloat162(l0, l1);
                }
            }
        }
    }
}

// ---------------- fp32 -> bf16 hi/lo split (external input only) ----------------
__global__ void k_split(const float* __restrict__ x, __nv_bfloat16* __restrict__ hi,
                        __nv_bfloat16* __restrict__ lo, int n)
{
    int i = blockIdx.x * blockDim.x + threadIdx.x;
    const int stride = gridDim.x * blockDim.x;
    for (; i < n; i += stride) {
        __nv_bfloat16 h, l;
        split_bf16(x[i], h, l);
        hi[i] = h; lo[i] = l;
    }
}

// transpose + split weights: W[K,N] fp32 -> th/tl[N,K] bf16 (into arena offset)
__global__ __launch_bounds__(256) void k_wsplit(
    const float* __restrict__ W, __nv_bfloat16* __restrict__ th,
    __nv_bfloat16* __restrict__ tl, int K, int N)
{
    __shared__ float tile[32][33];
    const int n0 = blockIdx.x * 32, k0 = blockIdx.y * 32;
    const int tx = threadIdx.x, ty = threadIdx.y;   // (32, 8)
    #pragma unroll
    for (int j = 0; j < 32; j += 8)
        tile[ty + j][tx] = W[(size_t)(k0 + ty + j) * N + n0 + tx];  // tile[k][n]
    __syncthreads();
    #pragma unroll
    for (int j = 0; j < 32; j += 8) {
        float v = tile[tx][ty + j];                 // k=tx, n=ty+j
        __nv_bfloat16 h, l;
        split_bf16(v, h, l);
        size_t o = (size_t)(n0 + ty + j) * K + k0 + tx;
        th[o] = h; tl[o] = l;
    }
}

// ---------------- helpers ----------------
__device__ __forceinline__ void atomicMaxF(float* addr, float val) {
    int* ia = (int*)addr;
    int old = *ia;
    while (__int_as_float(old) < val) {
        int assumed = old;
        old = atomicCAS(ia, assumed, __float_as_int(val));
        if (old == assumed) break;
    }
}

// ---------------- graph preprocessing ----------------
__global__ void k_csr_init() {
    int i = blockIdx.x * blockDim.x + threadIdx.x;
    if (i < NN) { g_indeg[i] = 0; g_cursor[i] = 0; }
    if (i < NG) { g_gstart[i] = 0; g_gend[i] = 0; }
}

__global__ void k_degree(const int* __restrict__ dst) {
    int e = blockIdx.x * blockDim.x + threadIdx.x;
    if (e < NE) atomicAdd(&g_indeg[dst[e]], 1);
}

__global__ __launch_bounds__(1024) void k_scan() {
    __shared__ int s[1024];
    int t = threadIdx.x;
    int base = t * 10;
    int vals[10];
    int local = 0;
    #pragma unroll
    for (int j = 0; j < 10; j++) {
        int idx = base + j;
        vals[j] = (idx < NN) ? g_indeg[idx] : 0;
        local += vals[j];
    }
    s[t] = local;
    __syncthreads();
    for (int off = 1; off < 1024; off <<= 1) {
        int v = (t >= off) ? s[t - off] : 0;
        __syncthreads();
        s[t] += v;
        __syncthreads();
    }
    int excl = (t == 0) ? 0 : s[t - 1];
    #pragma unroll
    for (int j = 0; j < 10; j++) {
        int idx = base + j;
        if (idx < NN) { g_off[idx] = excl; excl += vals[j]; }
    }
    if (t == 1023) g_off[NN] = s[1023];
}

__global__ void k_csr_fill(const int* __restrict__ dst) {
    int e = blockIdx.x * blockDim.x + threadIdx.x;
    if (e < NE) {
        int d = dst[e];
        int p = g_off[d] + atomicAdd(&g_cursor[d], 1);
        g_csr[p] = e;
    }
}

__global__ void k_bounds(const int* __restrict__ gid) {
    int i = blockIdx.x * blockDim.x + threadIdx.x;
    if (i < NN) {
        int g = gid[i];
        if (i == 0 || gid[i - 1] != g) g_gstart[g] = i;
        if (i == NN - 1 || gid[i + 1] != g) g_gend[g] = i + 1;
    }
}

// ---------------- GAT kernels ----------------
__global__ void k_attn_reset() {
    int i = blockIdx.x * blockDim.x + threadIdx.x;
    if (i < NN * HH) { g_emax[i] = -INFINITY; g_den[i] = 0.f; }
}

// per-node, per-head attention projections (float4 loads)
__global__ __launch_bounds__(128) void k_elr(
    const float* __restrict__ feat, const float* __restrict__ al,
    const float* __restrict__ ar)
{
    int n = blockIdx.x;
    int h = threadIdx.x >> 5;
    int lane = threadIdx.x & 31;
    const float4* f = (const float4*)(feat + (size_t)n * HD + h * DD);
    const float4* pal = (const float4*)(al + h * DD);
    const float4* par = (const float4*)(ar + h * DD);
    float sl = 0.f, sr = 0.f;
    #pragma unroll
    for (int i = lane; i < DD / 4; i += 32) {
        float4 v = f[i], a = pal[i], r = par[i];
        sl += v.x * a.x + v.y * a.y + v.z * a.z + v.w * a.w;
        sr += v.x * r.x + v.y * r.y + v.z * r.z + v.w * r.w;
    }
    #pragma unroll
    for (int o = 16; o; o >>= 1) {
        sl += __shfl_xor_sync(0xFFFFFFFFu, sl, o);
        sr += __shfl_xor_sync(0xFFFFFFFFu, sr, o);
    }
    if (lane == 0) { g_el[n * HH + h] = sl; g_er[n * HH + h] = sr; }
}

__global__ void k_logits(const int* __restrict__ src, const int* __restrict__ dst) {
    int idx = blockIdx.x * blockDim.x + threadIdx.x;
    if (idx < NE * HH) {
        int e = idx >> 2, h = idx & 3;
        float v = g_el[src[e] * HH + h] + g_er[dst[e] * HH + h];
        v = v > 0.f ? v : SLOPE * v;
        g_e[idx] = v;
        atomicMaxF(&g_emax[dst[e] * HH + h], v);
    }
}

__global__ void k_exden(const int* __restrict__ dst) {
    int idx = blockIdx.x * blockDim.x + threadIdx.x;
    if (idx < NE * HH) {
        int e = idx >> 2, h = idx & 3;
        float v = expf(g_e[idx] - g_emax[dst[e] * HH + h]);
        g_e[idx] = v;
        atomicAdd(&g_den[dst[e] * HH + h], v);
    }
}

// CSR gather aggregation: one block per dst node. Thread t owns 8 contiguous
// columns [t*8, t*8+8) -- all in head t>>6 (8 | 512). float4 loads; writes
// bf16 hi/lo split (consumed only as next GEMM's A operand).
__global__ __launch_bounds__(256) void k_aggregate(
    const float* __restrict__ feat, const int* __restrict__ src,
    const float* __restrict__ bias,
    __nv_bfloat16* __restrict__ ohi, __nv_bfloat16* __restrict__ olo)
{
    const int n = blockIdx.x;
    const int t = threadIdx.x;
    const int head = t >> 6;
    float inv = g_den[n * HH + head];
    inv = inv > 0.f ? 1.f / inv : 0.f;

    float4 a0 = make_float4(0.f, 0.f, 0.f, 0.f);
    float4 a1 = make_float4(0.f, 0.f, 0.f, 0.f);
    const int e0 = g_off[n], e1 = g_off[n + 1];
    for (int j = e0; j < e1; j++) {
        const int eid = g_csr[j];
        const int s = src[eid];
        const float c = g_e[eid * 4 + head] * inv;
        const float4* fs = (const float4*)(feat + (size_t)s * HD + t * 8);
        float4 f0 = fs[0], f1 = fs[1];
        a0.x += f0.x * c; a0.y += f0.y * c; a0.z += f0.z * c; a0.w += f0.w * c;
        a1.x += f1.x * c; a1.y += f1.y * c; a1.z += f1.z * c; a1.w += f1.w * c;
    }
    const float4* bp = (const float4*)(bias + t * 8);
    float4 b0 = bp[0], b1 = bp[1];
    float o[8] = {a0.x + b0.x, a0.y + b0.y, a0.z + b0.z, a0.w + b0.w,
                  a1.x + b1.x, a1.y + b1.y, a1.z + b1.z, a1.w + b1.w};
    __nv_bfloat162 hb[4], lb[4];
    #pragma unroll
    for (int q = 0; q < 4; q++) {
        __nv_bfloat16 h0, l0, h1, l1;
        split_bf16(o[2 * q], h0, l0);
        split_bf16(o[2 * q + 1], h1, l1);
        hb[q] = __nv_bfloat162(h0, h1);
        lb[q] = __nv_bfloat162(l0, l1);
    }
    const size_t idx = (size_t)n * HD + t * 8;
    *(uint4*)(ohi + idx) = *(uint4*)hb;
    *(uint4*)(olo + idx) = *(uint4*)lb;
}

// ---------------- pooling / head ----------------
// grid (NG, 4): each block reduces 128 columns of one graph
__global__ __launch_bounds__(128) void k_pool(
    const float* __restrict__ h, const float* __restrict__ gamma,
    const float* __restrict__ beta)
{
    int g = blockIdx.x;
    int c = blockIdx.y * 128 + threadIdx.x;
    int s0 = g_gstart[g], s1 = g_gend[g];
    float sum = 0.f;
    for (int i = s0; i < s1; i++) sum += h[(size_t)i * HF + c];
    float cnt = (float)((s1 - s0) > 1 ? (s1 - s0) : 1);
    float v = sum / cnt;
    v = v * rsqrtf(1.f + 1e-5f) * gamma[c] + beta[c];
    g_hg[g * HF + c] = v;
}

__global__ __launch_bounds__(512) void k_fc1(
    const float* __restrict__ W, const float* __restrict__ b)
{
    int g = blockIdx.x;
    int c = threadIdx.x;
    __shared__ float x[HF];
    x[c] = g_hg[g * HF + c];
    __syncthreads();
    float acc = b[c];
    for (int k = 0; k < HF; k++) acc += x[k] * W[k * HF + c];
    g_hg2[g * HF + c] = acc > 0.f ? acc : expm1f(acc);
}

__global__ void k_final(const float* __restrict__ Wf, const float* __restrict__ bf,
                        float* __restrict__ out)
{
    int t = threadIdx.x;          // 128 = 64 graphs * 2 classes
    int g = t >> 1, c = t & 1;
    float acc = bf[c];
    const float* x = g_hg2 + g * HF;
    for (int k = 0; k < HF; k++) acc += x[k] * Wf[k * 2 + c];
    out[g * 2 + c] = acc;
}

// ---------------- host orchestration ----------------
static void gat_layer(const float* feat, const float* al, const float* ar,
                      const float* b, const int* src, const int* dst,
                      __nv_bfloat16* ohi, __nv_bfloat16* olo)
{
    k_attn_reset<<<(NN * HH + 255) / 256, 256>>>();
    k_elr<<<NN, 128>>>(feat, al, ar);
    k_logits<<<(NE * HH + 255) / 256, 256>>>(src, dst);
    k_exden<<<(NE * HH + 255) / 256, 256>>>(dst);
    k_aggregate<<<NN, 256>>>(feat, src, b, ohi, olo);
}

static void run_gemm(const __nv_bfloat16* ah, const __nv_bfloat16* al,
                     const __nv_bfloat16* wth, const __nv_bfloat16* wtl,
                     const float* bias,
                     float* C, __nv_bfloat16* Chi, __nv_bfloat16* Clo,
                     int M, int N, int K, int act)
{
    tc_gemm<<<dim3(N / 128, (M + 255) / 256), 256, TC_SMEM>>>(
        ah, al, wth, wtl, bias, C, Chi, Clo, M, N, K, act);
}

extern "C" void kernel_launch(void* const* d_in, const int* in_sizes, int n_in,
                              void* d_out, int out_size)
{
    (void)in_sizes; (void)n_in; (void)out_size;
    const float* node_feat = (const float*)d_in[0];
    // d_in[1] = func_feat  : dead for output, skipped
    const float* W1   = (const float*)d_in[2];
    const float* al1  = (const float*)d_in[3];
    const float* ar1  = (const float*)d_in[4];
    const float* b1   = (const float*)d_in[5];
    const float* W2   = (const float*)d_in[6];
    const float* al2  = (const float*)d_in[7];
    const float* ar2  = (const float*)d_in[8];
    const float* b2   = (const float*)d_in[9];
    const float* Wfc  = (const float*)d_in[10];
    const float* bfc  = (const float*)d_in[11];
    // d_in[12] = Wfco, d_in[13] = bfco : dead for output, skipped
    const float* Wh   = (const float*)d_in[14];
    const float* bh   = (const float*)d_in[15];
    const float* gamma= (const float*)d_in[16];
    const float* beta = (const float*)d_in[17];
    const float* Whfc = (const float*)d_in[18];
    const float* bhfc = (const float*)d_in[19];
    const float* Wf   = (const float*)d_in[20];
    const float* bf   = (const float*)d_in[21];
    const int* src    = (const int*)d_in[22];
    const int* dst    = (const int*)d_in[23];
    const int* gid    = (const int*)d_in[24];

    float *feat, *h0;
    __nv_bfloat16 *ah, *al, *bhp, *blp, *wth, *wtl;
    cudaGetSymbolAddress((void**)&feat, g_feat);
    cudaGetSymbolAddress((void**)&h0,   g_h0);
    cudaGetSymbolAddress((void**)&ah,   g_ah);
    cudaGetSymbolAddress((void**)&al,   g_al);
    cudaGetSymbolAddress((void**)&bhp,  g_bh);
    cudaGetSymbolAddress((void**)&blp,  g_bl);
    cudaGetSymbolAddress((void**)&wth,  g_wth);
    cudaGetSymbolAddress((void**)&wtl,  g_wtl);

    cudaFuncSetAttribute(tc_gemm, cudaFuncAttributeMaxDynamicSharedMemorySize,
                         TC_SMEM);

    // ---- launch order chosen so tc_gemm is the 4th launch (ncu capture slot) ----
    // 1: W1 split   2: node_feat split   3: csr_init   4: tc_gemm (GEMM1)
    k_wsplit<<<dim3(2048 / 32, 768 / 32), dim3(32, 8)>>>(W1, wth + OFF_W1, wtl + OFF_W1, 768, 2048);
    k_split<<<4096, 256>>>(node_feat, ah, al, NN * EMB);
    k_csr_init<<<(NN + 255) / 256, 256>>>();
    run_gemm(ah, al, wth + OFF_W1, wtl + OFF_W1, nullptr,
             feat, nullptr, nullptr, NN, HD, EMB, 0);

    // ---- remaining graph preprocessing (must precede k_logits) ----
    k_degree<<<(NE + 255) / 256, 256>>>(dst);
    k_scan<<<1, 1024>>>();
    k_csr_fill<<<(NE + 255) / 256, 256>>>(dst);
    k_bounds<<<(NN + 255) / 256, 256>>>(gid);

    // ---- remaining weight splits ----
    k_wsplit<<<dim3(2048 / 32, 2048 / 32), dim3(32, 8)>>>(W2, wth + OFF_W2, wtl + OFF_W2, 2048, 2048);
    k_wsplit<<<dim3(512 / 32, 2048 / 32), dim3(32, 8)>>>(Wfc, wth + OFF_WFC, wtl + OFF_WFC, 2048, 512);
    for (int i = 0; i < 8; i++)
        k_wsplit<<<dim3(512 / 32, 512 / 32), dim3(32, 8)>>>(
            Wh + (size_t)i * HF * HF, wth + OFF_WH + (size_t)i * WH_SZ,
            wtl + OFF_WH + (size_t)i * WH_SZ, 512, 512);

    // ---- GAT layer 1 attention + aggregation ----
    gat_layer(feat, al1, ar1, b1, src, dst, bhp, blp);   // -> bf16 pair

    // ---- GAT layer 2 ----
    run_gemm(bhp, blp, wth + OFF_W2, wtl + OFF_W2, nullptr,
             feat, nullptr, nullptr, NN, HD, HD, 0);
    gat_layer(feat, al2, ar2, b2, src, dst, bhp, blp);   // -> bf16 pair

    // ---- h = elu(gat @ Wfc + bfc) -> bf16 pair ----
    run_gemm(bhp, blp, wth + OFF_WFC, wtl + OFF_WFC, bfc,
             nullptr, ah, al, NN, HF, HD, 1);

    // ---- 8 hidden layers (h branch only; h_func is dead) ----
    __nv_bfloat16 *cih = ah, *cil = al, *coh = bhp, *col = blp;
    for (int i = 0; i < 7; i++) {
        run_gemm(cih, cil, wth + OFF_WH + (size_t)i * WH_SZ,
                 wtl + OFF_WH + (size_t)i * WH_SZ, bh + i * HF,
                 nullptr, coh, col, NN, HF, HF, 1);
        __nv_bfloat16* t;
        t = cih; cih = coh; coh = t;
        t = cil; cil = col; col = t;
    }
    run_gemm(cih, cil, wth + OFF_WH + (size_t)7 * WH_SZ,
             wtl + OFF_WH + (size_t)7 * WH_SZ, bh + 7 * HF,
             h0, nullptr, nullptr, NN, HF, HF, 1);

    // ---- mean-pool per graph + BatchNorm (eval) folded ----
    k_pool<<<dim3(NG, 4), 128>>>(h0, gamma, beta);
    k_fc1<<<NG, 512>>>(Whfc, bhfc);
    k_final<<<1, 128>>>(Wf, bf, (float*)d_out);
}

// round 16
// speedup vs baseline: 1.3024x; 1.3024x over previous
#include <cuda_runtime.h>
#include <cuda_bf16.h>
#include <math.h>
#include <cstdint>

// ---------------- problem constants ----------------
#define NN 10000      // nodes
#define NE 80000      // edges
#define NG 64         // graphs
#define HH 4          // heads
#define DD 512        // per-head dim
#define HD 2048       // H*D
#define EMB 768
#define HF  512
#define SLOPE 0.2f

// ---------------- scratch (device globals, allocation-free) ----------------
__device__ __align__(128) float g_feat[(size_t)NN * HD];   // GAT fc output (fp32)
__device__ __align__(128) float g_h0  [(size_t)NN * HF];   // final hidden (fp32)
__device__ __align__(128) float g_e   [NE * HH];           // edge exp values
__device__ float g_el[NN * HH], g_er[NN * HH];
__device__ float g_den[NN * HH];                            // stores 1/den
__device__ int   g_indeg[NN], g_cursor[NN], g_off[NN + 1], g_csr[NE];
__device__ int   g_gstart[NG], g_gend[NG];
__device__ float g_hg[NG * HF], g_hg2[NG * HF];

// bf16 hi/lo pairs: activations (2 ping-pong pairs) + weight arena
#define WARENA 9000000
__device__ __align__(128) __nv_bfloat16 g_ah[(size_t)NN * HD];
__device__ __align__(128) __nv_bfloat16 g_al[(size_t)NN * HD];
__device__ __align__(128) __nv_bfloat16 g_bh[(size_t)NN * HD];
__device__ __align__(128) __nv_bfloat16 g_bl[(size_t)NN * HD];
__device__ __align__(128) __nv_bfloat16 g_wth[WARENA];
__device__ __align__(128) __nv_bfloat16 g_wtl[WARENA];

// weight arena offsets (elements; [N,K] row-major per weight)
#define OFF_W1   0
#define OFF_W2   (OFF_W1 + 2048 * 768)
#define OFF_WFC  (OFF_W2 + 2048 * 2048)
#define OFF_WH   (OFF_WFC + 512 * 2048)
#define WH_SZ    (512 * 512)

// ---------------- small PTX helpers (sm_80+ features only) ----------------
__device__ __forceinline__ uint32_t smem_u32(const void* p) {
    uint32_t a;
    asm("{ .reg .u64 t; cvta.to.shared.u64 t, %1; cvt.u32.u64 %0, t; }"
        : "=r"(a) : "l"(p));
    return a;
}

__device__ __forceinline__ void cp_async16(uint32_t saddr, const void* gaddr) {
    asm volatile("cp.async.cg.shared.global [%0], [%1], 16;"
                 :: "r"(saddr), "l"(gaddr));
}
#define CP_COMMIT()  asm volatile("cp.async.commit_group;" ::: "memory")
#define CP_WAIT(n)   asm volatile("cp.async.wait_group %0;" :: "n"(n) : "memory")

__device__ __forceinline__ void ldmx4(uint32_t* f, uint32_t saddr) {
    asm volatile("ldmatrix.sync.aligned.m8n8.x4.shared.b16 {%0,%1,%2,%3}, [%4];"
                 : "=r"(f[0]), "=r"(f[1]), "=r"(f[2]), "=r"(f[3]) : "r"(saddr));
}

__device__ __forceinline__ void mma16816(float* c, const uint32_t* a, const uint32_t* b) {
    asm volatile(
        "mma.sync.aligned.m16n8k16.row.col.f32.bf16.bf16.f32 "
        "{%0,%1,%2,%3}, {%4,%5,%6,%7}, {%8,%9}, {%0,%1,%2,%3};"
        : "+f"(c[0]), "+f"(c[1]), "+f"(c[2]), "+f"(c[3])
        : "r"(a[0]), "r"(a[1]), "r"(a[2]), "r"(a[3]), "r"(b[0]), "r"(b[1]));
}

__device__ __forceinline__ void split_bf16(float v, __nv_bfloat16& h, __nv_bfloat16& l) {
    h = __float2bfloat16(v);
    l = __float2bfloat16(v - __bfloat162float(h));
}

// ---------------- tensor-core GEMM via mma.sync (HMMA, bf16x3) ----------------
// R14 configuration (proven best): 128x128 tile/CTA, BK=32, cp.async
// double-buffered with ONE barrier per chunk, 8 warps (4m x 2n), warp 32x64.
// D = Ah*Bh + Ah*Bl + Al*Bh (fp32 accum), pass-major schedule.
#define TS   40                      // smem row stride (bf16 elems), 80B
#define TILE (128 * TS)              // one operand tile, elems
#define BUF  (4 * TILE)              // Ah,Al,Bh,Bl
#define TC_SMEM (2 * BUF * 2)        // bytes (two buffers)

__global__ __launch_bounds__(256, 2)
void tc_gemm(const __nv_bfloat16* __restrict__ Ah, const __nv_bfloat16* __restrict__ Al,
             const __nv_bfloat16* __restrict__ Bh, const __nv_bfloat16* __restrict__ Bl,
             const float* __restrict__ bias, float* __restrict__ C,
             __nv_bfloat16* __restrict__ Chi, __nv_bfloat16* __restrict__ Clo,
             int M, int N, int K, int act)
{
    extern __shared__ __nv_bfloat16 smem[];
    const uint32_t sb = smem_u32(smem);
    const int tid = threadIdx.x;
    const int lane = tid & 31;
    const int wid = tid >> 5;
    const int wm = wid >> 1, wn = wid & 1;
    const int m0 = wm * 32, n0 = wn * 64;
    const int bm = blockIdx.y * 128;
    const int bn = blockIdx.x * 128;
    const int NC = K >> 5;

    const int rb = tid >> 2;
    const int c16 = tid & 3;
    auto load_chunk = [&](int c, int b) {
        const int k0 = c << 5;
        const uint32_t bufb = sb + (uint32_t)b * BUF * 2;
        #pragma unroll
        for (int i = 0; i < 8; i++) {
            const int tile = i >> 1;                 // 0:Ah 1:Al 2:Bh 3:Bl
            const int r = rb + (i & 1) * 64;
            const uint32_t sa = bufb + (uint32_t)(tile * TILE + r * TS + c16 * 8) * 2;
            const int gk = k0 + c16 * 8;
            if (tile == 0) {
                int gr = bm + r; if (gr >= M) gr = M - 1;
                cp_async16(sa, Ah + (size_t)gr * K + gk);
            } else if (tile == 1) {
                int gr = bm + r; if (gr >= M) gr = M - 1;
                cp_async16(sa, Al + (size_t)gr * K + gk);
            } else if (tile == 2) {
                cp_async16(sa, Bh + (size_t)(bn + r) * K + gk);
            } else {
                cp_async16(sa, Bl + (size_t)(bn + r) * K + gk);
            }
        }
        CP_COMMIT();
    };

    float acc[2][8][4];
    #pragma unroll
    for (int mt = 0; mt < 2; mt++)
        #pragma unroll
        for (int nt = 0; nt < 8; nt++)
            #pragma unroll
            for (int q = 0; q < 4; q++) acc[mt][nt][q] = 0.f;

    load_chunk(0, 0);

    for (int c = 0; c < NC; c++) {
        const int b = c & 1;
        CP_WAIT(0);
        __syncthreads();
        if (c + 1 < NC) load_chunk(c + 1, 1 - b);

        const uint32_t bufb = sb + (uint32_t)b * BUF * 2;
        const uint32_t sAh = bufb;
        const uint32_t sAl = bufb + TILE * 2;
        const uint32_t sBh = bufb + 2 * TILE * 2;
        const uint32_t sBl = bufb + 3 * TILE * 2;

        #pragma unroll
        for (int ks = 0; ks < 2; ks++) {
            const int kk = ks * 16;
            uint32_t ahf[2][4], alf[2][4];
            const uint32_t aoff =
                (uint32_t)((m0 + (lane & 15)) * TS + kk + (lane >> 4) * 8) * 2;
            #pragma unroll
            for (int mt = 0; mt < 2; mt++) {
                ldmx4(ahf[mt], sAh + aoff + (uint32_t)(mt * 16 * TS) * 2);
                ldmx4(alf[mt], sAl + aoff + (uint32_t)(mt * 16 * TS) * 2);
            }
            const uint32_t boff =
                (uint32_t)((n0 + (lane & 7) + ((lane & 16) ? 8 : 0)) * TS
                           + kk + ((lane & 8) ? 8 : 0)) * 2;
            #pragma unroll
            for (int nph = 0; nph < 2; nph++) {
                uint32_t bhf[2][4], blf[2][4];
                #pragma unroll
                for (int p = 0; p < 2; p++) {
                    const uint32_t o =
                        boff + (uint32_t)((nph * 2 + p) * 16 * TS) * 2;
                    ldmx4(bhf[p], sBh + o);
                    ldmx4(blf[p], sBl + o);
                }
                #pragma unroll
                for (int p = 0; p < 2; p++) {
                    const int nt = (nph * 2 + p) * 2;
                    #pragma unroll
                    for (int mt = 0; mt < 2; mt++) {
                        mma16816(acc[mt][nt],     ahf[mt], bhf[p]);
                        mma16816(acc[mt][nt + 1], ahf[mt], bhf[p] + 2);
                    }
                }
                #pragma unroll
                for (int p = 0; p < 2; p++) {
                    const int nt = (nph * 2 + p) * 2;
                    #pragma unroll
                    for (int mt = 0; mt < 2; mt++) {
                        mma16816(acc[mt][nt],     ahf[mt], blf[p]);
                        mma16816(acc[mt][nt + 1], ahf[mt], blf[p] + 2);
                    }
                }
                #pragma unroll
                for (int p = 0; p < 2; p++) {
                    const int nt = (nph * 2 + p) * 2;
                    #pragma unroll
                    for (int mt = 0; mt < 2; mt++) {
                        mma16816(acc[mt][nt],     alf[mt], bhf[p]);
                        mma16816(acc[mt][nt + 1], alf[mt], bhf[p] + 2);
                    }
                }
            }
        }
    }

    // ---- epilogue ----
    #pragma unroll
    for (int mt = 0; mt < 2; mt++) {
        #pragma unroll
        for (int half = 0; half < 2; half++) {
            const int grow = bm + m0 + mt * 16 + (lane >> 2) + half * 8;
            if (grow >= M) continue;
            #pragma unroll
            for (int nt = 0; nt < 8; nt++) {
                const int gcol = bn + n0 + nt * 8 + (lane & 3) * 2;
                float v0 = acc[mt][nt][half * 2 + 0];
                float v1 = acc[mt][nt][half * 2 + 1];
                if (bias) { v0 += bias[gcol]; v1 += bias[gcol + 1]; }
                if (act) {
                    v0 = v0 > 0.f ? v0 : expm1f(v0);
                    v1 = v1 > 0.f ? v1 : expm1f(v1);
                }
                const size_t idx = (size_t)grow * N + gcol;
                if (C) *(float2*)(C + idx) = make_float2(v0, v1);
                if (Chi) {
                    __nv_bfloat16 h0, l0, h1, l1;
                    split_bf16(v0, h0, l0);
                    split_bf16(v1, h1, l1);
                    *(__nv_bfloat162*)(Chi + idx) = __nv_bfloat162(h0, h1);
                    *(__nv_bfloat162*)(Clo + idx) = __nv_bfloat162(l0, l1);
                }
            }
        }
    }
}

// ---------------- fp32 -> bf16 hi/lo split (external input only) ----------------
__global__ void k_split(const float* __restrict__ x, __nv_bfloat16* __restrict__ hi,
                        __nv_bfloat16* __restrict__ lo, int n)
{
    int i = blockIdx.x * blockDim.x + threadIdx.x;
    const int stride = gridDim.x * blockDim.x;
    for (; i < n; i += stride) {
        __nv_bfloat16 h, l;
        split_bf16(x[i], h, l);
        hi[i] = h; lo[i] = l;
    }
}

// transpose + split weights: W[K,N] fp32 -> th/tl[N,K] bf16 (into arena offset)
__global__ __launch_bounds__(256) void k_wsplit(
    const float* __restrict__ W, __nv_bfloat16* __restrict__ th,
    __nv_bfloat16* __restrict__ tl, int K, int N)
{
    __shared__ float tile[32][33];
    const int n0 = blockIdx.x * 32, k0 = blockIdx.y * 32;
    const int tx = threadIdx.x, ty = threadIdx.y;   // (32, 8)
    #pragma unroll
    for (int j = 0; j < 32; j += 8)
        tile[ty + j][tx] = W[(size_t)(k0 + ty + j) * N + n0 + tx];  // tile[k][n]
    __syncthreads();
    #pragma unroll
    for (int j = 0; j < 32; j += 8) {
        float v = tile[tx][ty + j];                 // k=tx, n=ty+j
        __nv_bfloat16 h, l;
        split_bf16(v, h, l);
        size_t o = (size_t)(n0 + ty + j) * K + k0 + tx;
        th[o] = h; tl[o] = l;
    }
}

// ---------------- graph preprocessing ----------------
__global__ void k_csr_init() {
    int i = blockIdx.x * blockDim.x + threadIdx.x;
    if (i < NN) { g_indeg[i] = 0; g_cursor[i] = 0; }
    if (i < NG) { g_gstart[i] = 0; g_gend[i] = 0; }
}

__global__ void k_degree(const int* __restrict__ dst) {
    int e = blockIdx.x * blockDim.x + threadIdx.x;
    if (e < NE) atomicAdd(&g_indeg[dst[e]], 1);
}

__global__ __launch_bounds__(1024) void k_scan() {
    __shared__ int s[1024];
    int t = threadIdx.x;
    int base = t * 10;
    int vals[10];
    int local = 0;
    #pragma unroll
    for (int j = 0; j < 10; j++) {
        int idx = base + j;
        vals[j] = (idx < NN) ? g_indeg[idx] : 0;
        local += vals[j];
    }
    s[t] = local;
    __syncthreads();
    for (int off = 1; off < 1024; off <<= 1) {
        int v = (t >= off) ? s[t - off] : 0;
        __syncthreads();
        s[t] += v;
        __syncthreads();
    }
    int excl = (t == 0) ? 0 : s[t - 1];
    #pragma unroll
    for (int j = 0; j < 10; j++) {
        int idx = base + j;
        if (idx < NN) { g_off[idx] = excl; excl += vals[j]; }
    }
    if (t == 1023) g_off[NN] = s[1023];
}

__global__ void k_csr_fill(const int* __restrict__ dst) {
    int e = blockIdx.x * blockDim.x + threadIdx.x;
    if (e < NE) {
        int d = dst[e];
        int p = g_off[d] + atomicAdd(&g_cursor[d], 1);
        g_csr[p] = e;
    }
}

__global__ void k_bounds(const int* __restrict__ gid) {
    int i = blockIdx.x * blockDim.x + threadIdx.x;
    if (i < NN) {
        int g = gid[i];
        if (i == 0 || gid[i - 1] != g) g_gstart[g] = i;
        if (i == NN - 1 || gid[i + 1] != g) g_gend[g] = i + 1;
    }
}

// ---------------- GAT kernels ----------------
// per-node, per-head attention projections (float4 loads)
__global__ __launch_bounds__(128) void k_elr(
    const float* __restrict__ feat, const float* __restrict__ al,
    const float* __restrict__ ar)
{
    int n = blockIdx.x;
    int h = threadIdx.x >> 5;
    int lane = threadIdx.x & 31;
    const float4* f = (const float4*)(feat + (size_t)n * HD + h * DD);
    const float4* pal = (const float4*)(al + h * DD);
    const float4* par = (const float4*)(ar + h * DD);
    float sl = 0.f, sr = 0.f;
    #pragma unroll
    for (int i = lane; i < DD / 4; i += 32) {
        float4 v = f[i], a = pal[i], r = par[i];
        sl += v.x * a.x + v.y * a.y + v.z * a.z + v.w * a.w;
        sr += v.x * r.x + v.y * r.y + v.z * r.z + v.w * r.w;
    }
    #pragma unroll
    for (int o = 16; o; o >>= 1) {
        sl += __shfl_xor_sync(0xFFFFFFFFu, sl, o);
        sr += __shfl_xor_sync(0xFFFFFFFFu, sr, o);
    }
    if (lane == 0) { g_el[n * HH + h] = sl; g_er[n * HH + h] = sr; }
}

// Fused per-node edge softmax: one warp per node, 4 heads vectorized.
// Two CSR passes: (1) per-head max via shuffle reduce, (2) exp + sum,
// writing exp values to g_e and 1/den to g_den. No atomics, no reset.
__global__ __launch_bounds__(256) void k_attn(const int* __restrict__ src)
{
    const int n = blockIdx.x * 8 + (threadIdx.x >> 5);
    if (n >= NN) return;
    const int lane = threadIdx.x & 31;
    const int e0 = g_off[n], e1 = g_off[n + 1];
    const float4 ern = *(const float4*)(g_er + n * 4);

    // pass 1: per-head max of leaky(el[s] + er[n])
    float4 mx = make_float4(-INFINITY, -INFINITY, -INFINITY, -INFINITY);
    for (int j = e0 + lane; j < e1; j += 32) {
        const int s = src[g_csr[j]];
        const float4 els = *(const float4*)(g_el + s * 4);
        float v0 = els.x + ern.x; v0 = v0 > 0.f ? v0 : SLOPE * v0;
        float v1 = els.y + ern.y; v1 = v1 > 0.f ? v1 : SLOPE * v1;
        float v2 = els.z + ern.z; v2 = v2 > 0.f ? v2 : SLOPE * v2;
        float v3 = els.w + ern.w; v3 = v3 > 0.f ? v3 : SLOPE * v3;
        mx.x = fmaxf(mx.x, v0); mx.y = fmaxf(mx.y, v1);
        mx.z = fmaxf(mx.z, v2); mx.w = fmaxf(mx.w, v3);
    }
    #pragma unroll
    for (int o = 16; o; o >>= 1) {
        mx.x = fmaxf(mx.x, __shfl_xor_sync(0xFFFFFFFFu, mx.x, o));
        mx.y = fmaxf(mx.y, __shfl_xor_sync(0xFFFFFFFFu, mx.y, o));
        mx.z = fmaxf(mx.z, __shfl_xor_sync(0xFFFFFFFFu, mx.z, o));
        mx.w = fmaxf(mx.w, __shfl_xor_sync(0xFFFFFFFFu, mx.w, o));
    }

    // pass 2: exp + sum; write exp values per edge
    float4 sm = make_float4(0.f, 0.f, 0.f, 0.f);
    for (int j = e0 + lane; j < e1; j += 32) {
        const int eid = g_csr[j];
        const int s = src[eid];
        const float4 els = *(const float4*)(g_el + s * 4);
        float v0 = els.x + ern.x; v0 = v0 > 0.f ? v0 : SLOPE * v0;
        float v1 = els.y + ern.y; v1 = v1 > 0.f ? v1 : SLOPE * v1;
        float v2 = els.z + ern.z; v2 = v2 > 0.f ? v2 : SLOPE * v2;
        float v3 = els.w + ern.w; v3 = v3 > 0.f ? v3 : SLOPE * v3;
        float e0x = expf(v0 - mx.x), e1x = expf(v1 - mx.y);
        float e2x = expf(v2 - mx.z), e3x = expf(v3 - mx.w);
        *(float4*)(g_e + (size_t)eid * 4) = make_float4(e0x, e1x, e2x, e3x);
        sm.x += e0x; sm.y += e1x; sm.z += e2x; sm.w += e3x;
    }
    #pragma unroll
    for (int o = 16; o; o >>= 1) {
        sm.x += __shfl_xor_sync(0xFFFFFFFFu, sm.x, o);
        sm.y += __shfl_xor_sync(0xFFFFFFFFu, sm.y, o);
        sm.z += __shfl_xor_sync(0xFFFFFFFFu, sm.z, o);
        sm.w += __shfl_xor_sync(0xFFFFFFFFu, sm.w, o);
    }
    if (lane == 0) {
        float4 inv;
        inv.x = sm.x > 0.f ? 1.f / sm.x : 0.f;
        inv.y = sm.y > 0.f ? 1.f / sm.y : 0.f;
        inv.z = sm.z > 0.f ? 1.f / sm.z : 0.f;
        inv.w = sm.w > 0.f ? 1.f / sm.w : 0.f;
        *(float4*)(g_den + n * 4) = inv;     // stores 1/den
    }
}

// CSR gather aggregation: one block per dst node. Thread t owns 8 contiguous
// columns [t*8, t*8+8) -- all in head t>>6. g_den holds 1/den already.
__global__ __launch_bounds__(256) void k_aggregate(
    const float* __restrict__ feat, const int* __restrict__ src,
    const float* __restrict__ bias,
    __nv_bfloat16* __restrict__ ohi, __nv_bfloat16* __restrict__ olo)
{
    const int n = blockIdx.x;
    const int t = threadIdx.x;
    const int head = t >> 6;
    const float inv = g_den[n * HH + head];

    float4 a0 = make_float4(0.f, 0.f, 0.f, 0.f);
    float4 a1 = make_float4(0.f, 0.f, 0.f, 0.f);
    const int e0 = g_off[n], e1 = g_off[n + 1];
    for (int j = e0; j < e1; j++) {
        const int eid = g_csr[j];
        const int s = src[eid];
        const float c = g_e[eid * 4 + head] * inv;
        const float4* fs = (const float4*)(feat + (size_t)s * HD + t * 8);
        float4 f0 = fs[0], f1 = fs[1];
        a0.x += f0.x * c; a0.y += f0.y * c; a0.z += f0.z * c; a0.w += f0.w * c;
        a1.x += f1.x * c; a1.y += f1.y * c; a1.z += f1.z * c; a1.w += f1.w * c;
    }
    const float4* bp = (const float4*)(bias + t * 8);
    float4 b0 = bp[0], b1 = bp[1];
    float o[8] = {a0.x + b0.x, a0.y + b0.y, a0.z + b0.z, a0.w + b0.w,
                  a1.x + b1.x, a1.y + b1.y, a1.z + b1.z, a1.w + b1.w};
    __nv_bfloat162 hb[4], lb[4];
    #pragma unroll
    for (int q = 0; q < 4; q++) {
        __nv_bfloat16 h0, l0, h1, l1;
        split_bf16(o[2 * q], h0, l0);
        split_bf16(o[2 * q + 1], h1, l1);
        hb[q] = __nv_bfloat162(h0, h1);
        lb[q] = __nv_bfloat162(l0, l1);
    }
    const size_t idx = (size_t)n * HD + t * 8;
    *(uint4*)(ohi + idx) = *(uint4*)hb;
    *(uint4*)(olo + idx) = *(uint4*)lb;
}

// ---------------- pooling / head ----------------
__global__ __launch_bounds__(128) void k_pool(
    const float* __restrict__ h, const float* __restrict__ gamma,
    const float* __restrict__ beta)
{
    int g = blockIdx.x;
    int c = blockIdx.y * 128 + threadIdx.x;
    int s0 = g_gstart[g], s1 = g_gend[g];
    float sum = 0.f;
    for (int i = s0; i < s1; i++) sum += h[(size_t)i * HF + c];
    float cnt = (float)((s1 - s0) > 1 ? (s1 - s0) : 1);
    float v = sum / cnt;
    v = v * rsqrtf(1.f + 1e-5f) * gamma[c] + beta[c];
    g_hg[g * HF + c] = v;
}

__global__ __launch_bounds__(512) void k_fc1(
    const float* __restrict__ W, const float* __restrict__ b)
{
    int g = blockIdx.x;
    int c = threadIdx.x;
    __shared__ float x[HF];
    x[c] = g_hg[g * HF + c];
    __syncthreads();
    float acc = b[c];
    for (int k = 0; k < HF; k++) acc += x[k] * W[k * HF + c];
    g_hg2[g * HF + c] = acc > 0.f ? acc : expm1f(acc);
}

__global__ void k_final(const float* __restrict__ Wf, const float* __restrict__ bf,
                        float* __restrict__ out)
{
    int t = threadIdx.x;          // 128 = 64 graphs * 2 classes
    int g = t >> 1, c = t & 1;
    float acc = bf[c];
    const float* x = g_hg2 + g * HF;
    for (int k = 0; k < HF; k++) acc += x[k] * Wf[k * 2 + c];
    out[g * 2 + c] = acc;
}

// ---------------- host orchestration ----------------
static void gat_layer(const float* feat, const float* al, const float* ar,
                      const float* b, const int* src, const int* dst,
                      __nv_bfloat16* ohi, __nv_bfloat16* olo)
{
    (void)dst;
    k_elr<<<NN, 128>>>(feat, al, ar);
    k_attn<<<(NN + 7) / 8, 256>>>(src);
    k_aggregate<<<NN, 256>>>(feat, src, b, ohi, olo);
}

static void run_gemm(const __nv_bfloat16* ah, const __nv_bfloat16* al,
                     const __nv_bfloat16* wth, const __nv_bfloat16* wtl,
                     const float* bias,
                     float* C, __nv_bfloat16* Chi, __nv_bfloat16* Clo,
                     int M, int N, int K, int act)
{
    tc_gemm<<<dim3(N / 128, (M + 127) / 128), 256, TC_SMEM>>>(
        ah, al, wth, wtl, bias, C, Chi, Clo, M, N, K, act);
}

extern "C" void kernel_launch(void* const* d_in, const int* in_sizes, int n_in,
                              void* d_out, int out_size)
{
    (void)in_sizes; (void)n_in; (void)out_size;
    const float* node_feat = (const float*)d_in[0];
    // d_in[1] = func_feat  : dead for output, skipped
    const float* W1   = (const float*)d_in[2];
    const float* al1  = (const float*)d_in[3];
    const float* ar1  = (const float*)d_in[4];
    const float* b1   = (const float*)d_in[5];
    const float* W2   = (const float*)d_in[6];
    const float* al2  = (const float*)d_in[7];
    const float* ar2  = (const float*)d_in[8];
    const float* b2   = (const float*)d_in[9];
    const float* Wfc  = (const float*)d_in[10];
    const float* bfc  = (const float*)d_in[11];
    // d_in[12] = Wfco, d_in[13] = bfco : dead for output, skipped
    const float* Wh   = (const float*)d_in[14];
    const float* bh   = (const float*)d_in[15];
    const float* gamma= (const float*)d_in[16];
    const float* beta = (const float*)d_in[17];
    const float* Whfc = (const float*)d_in[18];
    const float* bhfc = (const float*)d_in[19];
    const float* Wf   = (const float*)d_in[20];
    const float* bf   = (const float*)d_in[21];
    const int* src    = (const int*)d_in[22];
    const int* dst    = (const int*)d_in[23];
    const int* gid    = (const int*)d_in[24];

    float *feat, *h0;
    __nv_bfloat16 *ah, *al, *bhp, *blp, *wth, *wtl;
    cudaGetSymbolAddress((void**)&feat, g_feat);
    cudaGetSymbolAddress((void**)&h0,   g_h0);
    cudaGetSymbolAddress((void**)&ah,   g_ah);
    cudaGetSymbolAddress((void**)&al,   g_al);
    cudaGetSymbolAddress((void**)&bhp,  g_bh);
    cudaGetSymbolAddress((void**)&blp,  g_bl);
    cudaGetSymbolAddress((void**)&wth,  g_wth);
    cudaGetSymbolAddress((void**)&wtl,  g_wtl);

    cudaFuncSetAttribute(tc_gemm, cudaFuncAttributeMaxDynamicSharedMemorySize,
                         TC_SMEM);

    // ---- launch order chosen so tc_gemm is the 4th launch (ncu capture slot) ----
    // 1: W1 split   2: node_feat split   3: csr_init   4: tc_gemm (GEMM1)
    k_wsplit<<<dim3(2048 / 32, 768 / 32), dim3(32, 8)>>>(W1, wth + OFF_W1, wtl + OFF_W1, 768, 2048);
    k_split<<<4096, 256>>>(node_feat, ah, al, NN * EMB);
    k_csr_init<<<(NN + 255) / 256, 256>>>();
    run_gemm(ah, al, wth + OFF_W1, wtl + OFF_W1, nullptr,
             feat, nullptr, nullptr, NN, HD, EMB, 0);

    // ---- remaining graph preprocessing (must precede k_attn) ----
    k_degree<<<(NE + 255) / 256, 256>>>(dst);
    k_scan<<<1, 1024>>>();
    k_csr_fill<<<(NE + 255) / 256, 256>>>(dst);
    k_bounds<<<(NN + 255) / 256, 256>>>(gid);

    // ---- remaining weight splits ----
    k_wsplit<<<dim3(2048 / 32, 2048 / 32), dim3(32, 8)>>>(W2, wth + OFF_W2, wtl + OFF_W2, 2048, 2048);
    k_wsplit<<<dim3(512 / 32, 2048 / 32), dim3(32, 8)>>>(Wfc, wth + OFF_WFC, wtl + OFF_WFC, 2048, 512);
    for (int i = 0; i < 8; i++)
        k_wsplit<<<dim3(512 / 32, 512 / 32), dim3(32, 8)>>>(
            Wh + (size_t)i * HF * HF, wth + OFF_WH + (size_t)i * WH_SZ,
            wtl + OFF_WH + (size_t)i * WH_SZ, 512, 512);

    // ---- GAT layer 1 attention + aggregation ----
    gat_layer(feat, al1, ar1, b1, src, dst, bhp, blp);   // -> bf16 pair

    // ---- GAT layer 2 ----
    run_gemm(bhp, blp, wth + OFF_W2, wtl + OFF_W2, nullptr,
             feat, nullptr, nullptr, NN, HD, HD, 0);
    gat_layer(feat, al2, ar2, b2, src, dst, bhp, blp);   // -> bf16 pair

    // ---- h = elu(gat @ Wfc + bfc) -> bf16 pair ----
    run_gemm(bhp, blp, wth + OFF_WFC, wtl + OFF_WFC, bfc,
             nullptr, ah, al, NN, HF, HD, 1);

    // ---- 8 hidden layers (h branch only; h_func is dead) ----
    __nv_bfloat16 *cih = ah, *cil = al, *coh = bhp, *col = blp;
    for (int i = 0; i < 7; i++) {
        run_gemm(cih, cil, wth + OFF_WH + (size_t)i * WH_SZ,
                 wtl + OFF_WH + (size_t)i * WH_SZ, bh + i * HF,
                 nullptr, coh, col, NN, HF, HF, 1);
        __nv_bfloat16* t;
        t = cih; cih = coh; coh = t;
        t = cil; cil = col; col = t;
    }
    run_gemm(cih, cil, wth + OFF_WH + (size_t)7 * WH_SZ,
             wtl + OFF_WH + (size_t)7 * WH_SZ, bh + 7 * HF,
             h0, nullptr, nullptr, NN, HF, HF, 1);

    // ---- mean-pool per graph + BatchNorm (eval) folded ----
    k_pool<<<dim3(NG, 4), 128>>>(h0, gamma, beta);
    k_fc1<<<NG, 512>>>(Whfc, bhfc);
    k_final<<<1, 128>>>(Wf, bf, (float*)d_out);
}

// round 17
// speedup vs baseline: 1.3612x; 1.0451x over previous
#include <cuda_runtime.h>
#include <cuda_bf16.h>
#include <math.h>
#include <cstdint>

// ---------------- problem constants ----------------
#define NN 10000      // nodes
#define NE 80000      // edges
#define NG 64         // graphs
#define HH 4          // heads
#define DD 512        // per-head dim
#define HD 2048       // H*D
#define EMB 768
#define HF  512
#define SLOPE 0.2f

// ---------------- scratch (device globals, allocation-free) ----------------
__device__ __align__(128) float g_feat[(size_t)NN * HD];   // GAT fc output (fp32)
__device__ __align__(128) float g_h0  [(size_t)NN * HF];   // final hidden (fp32)
__device__ __align__(128) float g_e   [NE * HH];           // edge exp values
__device__ float g_el[NN * HH], g_er[NN * HH];
__device__ float g_den[NN * HH];                            // stores 1/den
__device__ int   g_indeg[NN], g_cursor[NN], g_off[NN + 1], g_csr[NE];
__device__ int   g_gstart[NG], g_gend[NG];
__device__ float g_hg[NG * HF], g_hg2[NG * HF];

// bf16 hi/lo pairs: activations (2 ping-pong pairs) + weight arena
#define WARENA 9000000
__device__ __align__(128) __nv_bfloat16 g_ah[(size_t)NN * HD];
__device__ __align__(128) __nv_bfloat16 g_al[(size_t)NN * HD];
__device__ __align__(128) __nv_bfloat16 g_bh[(size_t)NN * HD];
__device__ __align__(128) __nv_bfloat16 g_bl[(size_t)NN * HD];
__device__ __align__(128) __nv_bfloat16 g_wth[WARENA];
__device__ __align__(128) __nv_bfloat16 g_wtl[WARENA];

// weight arena offsets (elements; [N,K] row-major per weight)
#define OFF_W1   0
#define OFF_W2   (OFF_W1 + 2048 * 768)
#define OFF_WFC  (OFF_W2 + 2048 * 2048)
#define OFF_WH   (OFF_WFC + 512 * 2048)
#define WH_SZ    (512 * 512)

// ---------------- small PTX helpers (sm_80+ features only) ----------------
__device__ __forceinline__ uint32_t smem_u32(const void* p) {
    uint32_t a;
    asm("{ .reg .u64 t; cvta.to.shared.u64 t, %1; cvt.u32.u64 %0, t; }"
        : "=r"(a) : "l"(p));
    return a;
}

__device__ __forceinline__ void cp_async16(uint32_t saddr, const void* gaddr) {
    asm volatile("cp.async.cg.shared.global [%0], [%1], 16;"
                 :: "r"(saddr), "l"(gaddr));
}
#define CP_COMMIT()  asm volatile("cp.async.commit_group;" ::: "memory")
#define CP_WAIT(n)   asm volatile("cp.async.wait_group %0;" :: "n"(n) : "memory")

__device__ __forceinline__ void ldmx4(uint32_t* f, uint32_t saddr) {
    asm volatile("ldmatrix.sync.aligned.m8n8.x4.shared.b16 {%0,%1,%2,%3}, [%4];"
                 : "=r"(f[0]), "=r"(f[1]), "=r"(f[2]), "=r"(f[3]) : "r"(saddr));
}

__device__ __forceinline__ void mma16816(float* c, const uint32_t* a, const uint32_t* b) {
    asm volatile(
        "mma.sync.aligned.m16n8k16.row.col.f32.bf16.bf16.f32 "
        "{%0,%1,%2,%3}, {%4,%5,%6,%7}, {%8,%9}, {%0,%1,%2,%3};"
        : "+f"(c[0]), "+f"(c[1]), "+f"(c[2]), "+f"(c[3])
        : "r"(a[0]), "r"(a[1]), "r"(a[2]), "r"(a[3]), "r"(b[0]), "r"(b[1]));
}

__device__ __forceinline__ void split_bf16(float v, __nv_bfloat16& h, __nv_bfloat16& l) {
    h = __float2bfloat16(v);
    l = __float2bfloat16(v - __bfloat162float(h));
}

__device__ __forceinline__ void epi_store(
    float v0, float v1, const float* bias, int act, int gcol, size_t idx,
    float* C, __nv_bfloat16* Chi, __nv_bfloat16* Clo)
{
    if (bias) { v0 += bias[gcol]; v1 += bias[gcol + 1]; }
    if (act) {
        v0 = v0 > 0.f ? v0 : expm1f(v0);
        v1 = v1 > 0.f ? v1 : expm1f(v1);
    }
    if (C) *(float2*)(C + idx) = make_float2(v0, v1);
    if (Chi) {
        __nv_bfloat16 h0, l0, h1, l1;
        split_bf16(v0, h0, l0);
        split_bf16(v1, h1, l1);
        *(__nv_bfloat162*)(Chi + idx) = __nv_bfloat162(h0, h1);
        *(__nv_bfloat162*)(Clo + idx) = __nv_bfloat162(l0, l1);
    }
}

// ---------------- tensor-core GEMM via mma.sync (HMMA, bf16x3) ----------------
// Large-tile variant (proven R14 config): 128x128 tile/CTA, BK=32, cp.async
// double-buffered with ONE barrier per chunk, 8 warps (4m x 2n), warp 32x64.
// D = Ah*Bh + Ah*Bl + Al*Bh (fp32 accum), pass-major schedule.
#define TS   40                      // smem row stride (bf16 elems), 80B
#define TILE (128 * TS)              // one operand tile, elems
#define BUF  (4 * TILE)              // Ah,Al,Bh,Bl
#define TC_SMEM (2 * BUF * 2)        // bytes (two buffers)

__global__ __launch_bounds__(256, 2)
void tc_gemm(const __nv_bfloat16* __restrict__ Ah, const __nv_bfloat16* __restrict__ Al,
             const __nv_bfloat16* __restrict__ Bh, const __nv_bfloat16* __restrict__ Bl,
             const float* __restrict__ bias, float* __restrict__ C,
             __nv_bfloat16* __restrict__ Chi, __nv_bfloat16* __restrict__ Clo,
             int M, int N, int K, int act)
{
    extern __shared__ __nv_bfloat16 smem[];
    const uint32_t sb = smem_u32(smem);
    const int tid = threadIdx.x;
    const int lane = tid & 31;
    const int wid = tid >> 5;
    const int wm = wid >> 1, wn = wid & 1;
    const int m0 = wm * 32, n0 = wn * 64;
    const int bm = blockIdx.y * 128;
    const int bn = blockIdx.x * 128;
    const int NC = K >> 5;

    const int rb = tid >> 2;
    const int c16 = tid & 3;
    auto load_chunk = [&](int c, int b) {
        const int k0 = c << 5;
        const uint32_t bufb = sb + (uint32_t)b * BUF * 2;
        #pragma unroll
        for (int i = 0; i < 8; i++) {
            const int tile = i >> 1;                 // 0:Ah 1:Al 2:Bh 3:Bl
            const int r = rb + (i & 1) * 64;
            const uint32_t sa = bufb + (uint32_t)(tile * TILE + r * TS + c16 * 8) * 2;
            const int gk = k0 + c16 * 8;
            if (tile == 0) {
                int gr = bm + r; if (gr >= M) gr = M - 1;
                cp_async16(sa, Ah + (size_t)gr * K + gk);
            } else if (tile == 1) {
                int gr = bm + r; if (gr >= M) gr = M - 1;
                cp_async16(sa, Al + (size_t)gr * K + gk);
            } else if (tile == 2) {
                cp_async16(sa, Bh + (size_t)(bn + r) * K + gk);
            } else {
                cp_async16(sa, Bl + (size_t)(bn + r) * K + gk);
            }
        }
        CP_COMMIT();
    };

    float acc[2][8][4];
    #pragma unroll
    for (int mt = 0; mt < 2; mt++)
        #pragma unroll
        for (int nt = 0; nt < 8; nt++)
            #pragma unroll
            for (int q = 0; q < 4; q++) acc[mt][nt][q] = 0.f;

    load_chunk(0, 0);

    for (int c = 0; c < NC; c++) {
        const int b = c & 1;
        CP_WAIT(0);
        __syncthreads();
        if (c + 1 < NC) load_chunk(c + 1, 1 - b);

        const uint32_t bufb = sb + (uint32_t)b * BUF * 2;
        const uint32_t sAh = bufb;
        const uint32_t sAl = bufb + TILE * 2;
        const uint32_t sBh = bufb + 2 * TILE * 2;
        const uint32_t sBl = bufb + 3 * TILE * 2;

        #pragma unroll
        for (int ks = 0; ks < 2; ks++) {
            const int kk = ks * 16;
            uint32_t ahf[2][4], alf[2][4];
            const uint32_t aoff =
                (uint32_t)((m0 + (lane & 15)) * TS + kk + (lane >> 4) * 8) * 2;
            #pragma unroll
            for (int mt = 0; mt < 2; mt++) {
                ldmx4(ahf[mt], sAh + aoff + (uint32_t)(mt * 16 * TS) * 2);
                ldmx4(alf[mt], sAl + aoff + (uint32_t)(mt * 16 * TS) * 2);
            }
            const uint32_t boff =
                (uint32_t)((n0 + (lane & 7) + ((lane & 16) ? 8 : 0)) * TS
                           + kk + ((lane & 8) ? 8 : 0)) * 2;
            #pragma unroll
            for (int nph = 0; nph < 2; nph++) {
                uint32_t bhf[2][4], blf[2][4];
                #pragma unroll
                for (int p = 0; p < 2; p++) {
                    const uint32_t o =
                        boff + (uint32_t)((nph * 2 + p) * 16 * TS) * 2;
                    ldmx4(bhf[p], sBh + o);
                    ldmx4(blf[p], sBl + o);
                }
                #pragma unroll
                for (int p = 0; p < 2; p++) {
                    const int nt = (nph * 2 + p) * 2;
                    #pragma unroll
                    for (int mt = 0; mt < 2; mt++) {
                        mma16816(acc[mt][nt],     ahf[mt], bhf[p]);
                        mma16816(acc[mt][nt + 1], ahf[mt], bhf[p] + 2);
                    }
                }
                #pragma unroll
                for (int p = 0; p < 2; p++) {
                    const int nt = (nph * 2 + p) * 2;
                    #pragma unroll
                    for (int mt = 0; mt < 2; mt++) {
                        mma16816(acc[mt][nt],     ahf[mt], blf[p]);
                        mma16816(acc[mt][nt + 1], ahf[mt], blf[p] + 2);
                    }
                }
                #pragma unroll
                for (int p = 0; p < 2; p++) {
                    const int nt = (nph * 2 + p) * 2;
                    #pragma unroll
                    for (int mt = 0; mt < 2; mt++) {
                        mma16816(acc[mt][nt],     alf[mt], bhf[p]);
                        mma16816(acc[mt][nt + 1], alf[mt], bhf[p] + 2);
                    }
                }
            }
        }
    }

    #pragma unroll
    for (int mt = 0; mt < 2; mt++) {
        #pragma unroll
        for (int half = 0; half < 2; half++) {
            const int grow = bm + m0 + mt * 16 + (lane >> 2) + half * 8;
            if (grow >= M) continue;
            #pragma unroll
            for (int nt = 0; nt < 8; nt++) {
                const int gcol = bn + n0 + nt * 8 + (lane & 3) * 2;
                epi_store(acc[mt][nt][half * 2], acc[mt][nt][half * 2 + 1],
                          bias, act, gcol, (size_t)grow * N + gcol, C, Chi, Clo);
            }
        }
    }
}

// ---------------- small-tile GEMM: BM=64, BN=128, 3 CTAs/SM ----------------
// For small-N GEMMs (N=512) where 128x128 tiling gives 316 CTAs on 296 slots
// (53% wave efficiency). 628 CTAs at 3 CTAs/SM (24 warps) -> better balance
// and latency hiding. 8 warps as 2m x 4n, warp 32x32, acc = 32 regs.
#define TILE_SA (64 * TS)
#define TILE_SB (128 * TS)
#define BUF_S   (2 * TILE_SA + 2 * TILE_SB)
#define TC_SMEM_S (2 * BUF_S * 2)        // 61440 bytes

__global__ __launch_bounds__(256, 3)
void tc_gemm_s(const __nv_bfloat16* __restrict__ Ah, const __nv_bfloat16* __restrict__ Al,
               const __nv_bfloat16* __restrict__ Bh, const __nv_bfloat16* __restrict__ Bl,
               const float* __restrict__ bias, float* __restrict__ C,
               __nv_bfloat16* __restrict__ Chi, __nv_bfloat16* __restrict__ Clo,
               int M, int N, int K, int act)
{
    extern __shared__ __nv_bfloat16 smem[];
    const uint32_t sb = smem_u32(smem);
    const int tid = threadIdx.x;
    const int lane = tid & 31;
    const int wid = tid >> 5;
    const int wm = wid >> 2, wn = wid & 3;
    const int m0 = wm * 32, n0 = wn * 32;
    const int bm = blockIdx.y * 64;
    const int bn = blockIdx.x * 128;
    const int NC = K >> 5;

    auto load_chunk = [&](int c, int b) {
        const int k0 = c << 5;
        const uint32_t base = sb + (uint32_t)b * BUF_S * 2;
        // A: 2 tiles x 64 rows x 4 chunks = 512
        #pragma unroll
        for (int i = 0; i < 2; i++) {
            const int ci = i * 256 + tid;
            const int tile = ci >> 8;
            const int row = (ci >> 2) & 63;
            const int c4 = ci & 3;
            const uint32_t sa = base + (uint32_t)(tile * TILE_SA + row * TS + c4 * 8) * 2;
            int gr = bm + row; if (gr >= M) gr = M - 1;
            cp_async16(sa, (tile ? Al : Ah) + (size_t)gr * K + k0 + c4 * 8);
        }
        // B: 2 tiles x 128 rows x 4 chunks = 1024
        #pragma unroll
        for (int i = 0; i < 4; i++) {
            const int ci = i * 256 + tid;
            const int tile = ci >> 9;
            const int row = (ci >> 2) & 127;
            const int c4 = ci & 3;
            const uint32_t sa = base +
                (uint32_t)(2 * TILE_SA + tile * TILE_SB + row * TS + c4 * 8) * 2;
            cp_async16(sa, (tile ? Bl : Bh) + (size_t)(bn + row) * K + k0 + c4 * 8);
        }
        CP_COMMIT();
    };

    float acc[2][4][4];
    #pragma unroll
    for (int mt = 0; mt < 2; mt++)
        #pragma unroll
        for (int nt = 0; nt < 4; nt++)
            #pragma unroll
            for (int q = 0; q < 4; q++) acc[mt][nt][q] = 0.f;

    load_chunk(0, 0);

    for (int c = 0; c < NC; c++) {
        const int b = c & 1;
        CP_WAIT(0);
        __syncthreads();
        if (c + 1 < NC) load_chunk(c + 1, 1 - b);

        const uint32_t bufb = sb + (uint32_t)b * BUF_S * 2;
        const uint32_t sAh = bufb;
        const uint32_t sAl = bufb + TILE_SA * 2;
        const uint32_t sBh = bufb + 2 * TILE_SA * 2;
        const uint32_t sBl = bufb + (2 * TILE_SA + TILE_SB) * 2;

        #pragma unroll
        for (int ks = 0; ks < 2; ks++) {
            const int kk = ks * 16;
            uint32_t ahf[2][4], alf[2][4];
            const uint32_t aoff =
                (uint32_t)((m0 + (lane & 15)) * TS + kk + (lane >> 4) * 8) * 2;
            #pragma unroll
            for (int mt = 0; mt < 2; mt++) {
                ldmx4(ahf[mt], sAh + aoff + (uint32_t)(mt * 16 * TS) * 2);
                ldmx4(alf[mt], sAl + aoff + (uint32_t)(mt * 16 * TS) * 2);
            }
            const uint32_t boff =
                (uint32_t)((n0 + (lane & 7) + ((lane & 16) ? 8 : 0)) * TS
                           + kk + ((lane & 8) ? 8 : 0)) * 2;
            // warp covers 32 cols = 2 nph of 16 cols (2 n-tiles each)
            #pragma unroll
            for (int nph = 0; nph < 2; nph++) {
                uint32_t bhf[4], blf[4];
                const uint32_t o = boff + (uint32_t)(nph * 16 * TS) * 2;
                ldmx4(bhf, sBh + o);
                ldmx4(blf, sBl + o);
                const int nt = nph * 2;
                // pass 1: Ah*Bh (4 distinct accs)
                #pragma unroll
                for (int mt = 0; mt < 2; mt++) {
                    mma16816(acc[mt][nt],     ahf[mt], bhf);
                    mma16816(acc[mt][nt + 1], ahf[mt], bhf + 2);
                }
                // pass 2: Ah*Bl
                #pragma unroll
                for (int mt = 0; mt < 2; mt++) {
                    mma16816(acc[mt][nt],     ahf[mt], blf);
                    mma16816(acc[mt][nt + 1], ahf[mt], blf + 2);
                }
                // pass 3: Al*Bh
                #pragma unroll
                for (int mt = 0; mt < 2; mt++) {
                    mma16816(acc[mt][nt],     alf[mt], bhf);
                    mma16816(acc[mt][nt + 1], alf[mt], bhf + 2);
                }
            }
        }
    }

    #pragma unroll
    for (int mt = 0; mt < 2; mt++) {
        #pragma unroll
        for (int half = 0; half < 2; half++) {
            const int grow = bm + m0 + mt * 16 + (lane >> 2) + half * 8;
            if (grow >= M) continue;
            #pragma unroll
            for (int nt = 0; nt < 4; nt++) {
                const int gcol = bn + n0 + nt * 8 + (lane & 3) * 2;
                epi_store(acc[mt][nt][half * 2], acc[mt][nt][half * 2 + 1],
                          bias, act, gcol, (size_t)grow * N + gcol, C, Chi, Clo);
            }
        }
    }
}

// ---------------- fp32 -> bf16 hi/lo split (external input only) ----------------
__global__ void k_split(const float* __restrict__ x, __nv_bfloat16* __restrict__ hi,
                        __nv_bfloat16* __restrict__ lo, int n)
{
    int i = blockIdx.x * blockDim.x + threadIdx.x;
    const int stride = gridDim.x * blockDim.x;
    for (; i < n; i += stride) {
        __nv_bfloat16 h, l;
        split_bf16(x[i], h, l);
        hi[i] = h; lo[i] = l;
    }
}

// transpose + split weights: W[K,N] fp32 -> th/tl[N,K] bf16 (into arena offset)
__global__ __launch_bounds__(256) void k_wsplit(
    const float* __restrict__ W, __nv_bfloat16* __restrict__ th,
    __nv_bfloat16* __restrict__ tl, int K, int N)
{
    __shared__ float tile[32][33];
    const int n0 = blockIdx.x * 32, k0 = blockIdx.y * 32;
    const int tx = threadIdx.x, ty = threadIdx.y;   // (32, 8)
    #pragma unroll
    for (int j = 0; j < 32; j += 8)
        tile[ty + j][tx] = W[(size_t)(k0 + ty + j) * N + n0 + tx];  // tile[k][n]
    __syncthreads();
    #pragma unroll
    for (int j = 0; j < 32; j += 8) {
        float v = tile[tx][ty + j];                 // k=tx, n=ty+j
        __nv_bfloat16 h, l;
        split_bf16(v, h, l);
        size_t o = (size_t)(n0 + ty + j) * K + k0 + tx;
        th[o] = h; tl[o] = l;
    }
}

// ---------------- graph preprocessing ----------------
__global__ void k_csr_init() {
    int i = blockIdx.x * blockDim.x + threadIdx.x;
    if (i < NN) { g_indeg[i] = 0; g_cursor[i] = 0; }
    if (i < NG) { g_gstart[i] = 0; g_gend[i] = 0; }
}

__global__ void k_degree(const int* __restrict__ dst) {
    int e = blockIdx.x * blockDim.x + threadIdx.x;
    if (e < NE) atomicAdd(&g_indeg[dst[e]], 1);
}

__global__ __launch_bounds__(1024) void k_scan() {
    __shared__ int s[1024];
    int t = threadIdx.x;
    int base = t * 10;
    int vals[10];
    int local = 0;
    #pragma unroll
    for (int j = 0; j < 10; j++) {
        int idx = base + j;
        vals[j] = (idx < NN) ? g_indeg[idx] : 0;
        local += vals[j];
    }
    s[t] = local;
    __syncthreads();
    for (int off = 1; off < 1024; off <<= 1) {
        int v = (t >= off) ? s[t - off] : 0;
        __syncthreads();
        s[t] += v;
        __syncthreads();
    }
    int excl = (t == 0) ? 0 : s[t - 1];
    #pragma unroll
    for (int j = 0; j < 10; j++) {
        int idx = base + j;
        if (idx < NN) { g_off[idx] = excl; excl += vals[j]; }
    }
    if (t == 1023) g_off[NN] = s[1023];
}

__global__ void k_csr_fill(const int* __restrict__ dst) {
    int e = blockIdx.x * blockDim.x + threadIdx.x;
    if (e < NE) {
        int d = dst[e];
        int p = g_off[d] + atomicAdd(&g_cursor[d], 1);
        g_csr[p] = e;
    }
}

__global__ void k_bounds(const int* __restrict__ gid) {
    int i = blockIdx.x * blockDim.x + threadIdx.x;
    if (i < NN) {
        int g = gid[i];
        if (i == 0 || gid[i - 1] != g) g_gstart[g] = i;
        if (i == NN - 1 || gid[i + 1] != g) g_gend[g] = i + 1;
    }
}

// ---------------- GAT kernels ----------------
__global__ __launch_bounds__(128) void k_elr(
    const float* __restrict__ feat, const float* __restrict__ al,
    const float* __restrict__ ar)
{
    int n = blockIdx.x;
    int h = threadIdx.x >> 5;
    int lane = threadIdx.x & 31;
    const float4* f = (const float4*)(feat + (size_t)n * HD + h * DD);
    const float4* pal = (const float4*)(al + h * DD);
    const float4* par = (const float4*)(ar + h * DD);
    float sl = 0.f, sr = 0.f;
    #pragma unroll
    for (int i = lane; i < DD / 4; i += 32) {
        float4 v = f[i], a = pal[i], r = par[i];
        sl += v.x * a.x + v.y * a.y + v.z * a.z + v.w * a.w;
        sr += v.x * r.x + v.y * r.y + v.z * r.z + v.w * r.w;
    }
    #pragma unroll
    for (int o = 16; o; o >>= 1) {
        sl += __shfl_xor_sync(0xFFFFFFFFu, sl, o);
        sr += __shfl_xor_sync(0xFFFFFFFFu, sr, o);
    }
    if (lane == 0) { g_el[n * HH + h] = sl; g_er[n * HH + h] = sr; }
}

// Fused per-node edge softmax: one warp per node, 4 heads vectorized.
__global__ __launch_bounds__(256) void k_attn(const int* __restrict__ src)
{
    const int n = blockIdx.x * 8 + (threadIdx.x >> 5);
    if (n >= NN) return;
    const int lane = threadIdx.x & 31;
    const int e0 = g_off[n], e1 = g_off[n + 1];
    const float4 ern = *(const float4*)(g_er + n * 4);

    float4 mx = make_float4(-INFINITY, -INFINITY, -INFINITY, -INFINITY);
    for (int j = e0 + lane; j < e1; j += 32) {
        const int s = src[g_csr[j]];
        const float4 els = *(const float4*)(g_el + s * 4);
        float v0 = els.x + ern.x; v0 = v0 > 0.f ? v0 : SLOPE * v0;
        float v1 = els.y + ern.y; v1 = v1 > 0.f ? v1 : SLOPE * v1;
        float v2 = els.z + ern.z; v2 = v2 > 0.f ? v2 : SLOPE * v2;
        float v3 = els.w + ern.w; v3 = v3 > 0.f ? v3 : SLOPE * v3;
        mx.x = fmaxf(mx.x, v0); mx.y = fmaxf(mx.y, v1);
        mx.z = fmaxf(mx.z, v2); mx.w = fmaxf(mx.w, v3);
    }
    #pragma unroll
    for (int o = 16; o; o >>= 1) {
        mx.x = fmaxf(mx.x, __shfl_xor_sync(0xFFFFFFFFu, mx.x, o));
        mx.y = fmaxf(mx.y, __shfl_xor_sync(0xFFFFFFFFu, mx.y, o));
        mx.z = fmaxf(mx.z, __shfl_xor_sync(0xFFFFFFFFu, mx.z, o));
        mx.w = fmaxf(mx.w, __shfl_xor_sync(0xFFFFFFFFu, mx.w, o));
    }

    float4 sm = make_float4(0.f, 0.f, 0.f, 0.f);
    for (int j = e0 + lane; j < e1; j += 32) {
        const int eid = g_csr[j];
        const int s = src[eid];
        const float4 els = *(const float4*)(g_el + s * 4);
        float v0 = els.x + ern.x; v0 = v0 > 0.f ? v0 : SLOPE * v0;
        float v1 = els.y + ern.y; v1 = v1 > 0.f ? v1 : SLOPE * v1;
        float v2 = els.z + ern.z; v2 = v2 > 0.f ? v2 : SLOPE * v2;
        float v3 = els.w + ern.w; v3 = v3 > 0.f ? v3 : SLOPE * v3;
        float e0x = expf(v0 - mx.x), e1x = expf(v1 - mx.y);
        float e2x = expf(v2 - mx.z), e3x = expf(v3 - mx.w);
        *(float4*)(g_e + (size_t)eid * 4) = make_float4(e0x, e1x, e2x, e3x);
        sm.x += e0x; sm.y += e1x; sm.z += e2x; sm.w += e3x;
    }
    #pragma unroll
    for (int o = 16; o; o >>= 1) {
        sm.x += __shfl_xor_sync(0xFFFFFFFFu, sm.x, o);
        sm.y += __shfl_xor_sync(0xFFFFFFFFu, sm.y, o);
        sm.z += __shfl_xor_sync(0xFFFFFFFFu, sm.z, o);
        sm.w += __shfl_xor_sync(0xFFFFFFFFu, sm.w, o);
    }
    if (lane == 0) {
        float4 inv;
        inv.x = sm.x > 0.f ? 1.f / sm.x : 0.f;
        inv.y = sm.y > 0.f ? 1.f / sm.y : 0.f;
        inv.z = sm.z > 0.f ? 1.f / sm.z : 0.f;
        inv.w = sm.w > 0.f ? 1.f / sm.w : 0.f;
        *(float4*)(g_den + n * 4) = inv;     // stores 1/den
    }
}

// CSR gather aggregation: one block per dst node.
__global__ __launch_bounds__(256) void k_aggregate(
    const float* __restrict__ feat, const int* __restrict__ src,
    const float* __restrict__ bias,
    __nv_bfloat16* __restrict__ ohi, __nv_bfloat16* __restrict__ olo)
{
    const int n = blockIdx.x;
    const int t = threadIdx.x;
    const int head = t >> 6;
    const float inv = g_den[n * HH + head];

    float4 a0 = make_float4(0.f, 0.f, 0.f, 0.f);
    float4 a1 = make_float4(0.f, 0.f, 0.f, 0.f);
    const int e0 = g_off[n], e1 = g_off[n + 1];
    for (int j = e0; j < e1; j++) {
        const int eid = g_csr[j];
        const int s = src[eid];
        const float c = g_e[eid * 4 + head] * inv;
        const float4* fs = (const float4*)(feat + (size_t)s * HD + t * 8);
        float4 f0 = fs[0], f1 = fs[1];
        a0.x += f0.x * c; a0.y += f0.y * c; a0.z += f0.z * c; a0.w += f0.w * c;
        a1.x += f1.x * c; a1.y += f1.y * c; a1.z += f1.z * c; a1.w += f1.w * c;
    }
    const float4* bp = (const float4*)(bias + t * 8);
    float4 b0 = bp[0], b1 = bp[1];
    float o[8] = {a0.x + b0.x, a0.y + b0.y, a0.z + b0.z, a0.w + b0.w,
                  a1.x + b1.x, a1.y + b1.y, a1.z + b1.z, a1.w + b1.w};
    __nv_bfloat162 hb[4], lb[4];
    #pragma unroll
    for (int q = 0; q < 4; q++) {
        __nv_bfloat16 h0, l0, h1, l1;
        split_bf16(o[2 * q], h0, l0);
        split_bf16(o[2 * q + 1], h1, l1);
        hb[q] = __nv_bfloat162(h0, h1);
        lb[q] = __nv_bfloat162(l0, l1);
    }
    const size_t idx = (size_t)n * HD + t * 8;
    *(uint4*)(ohi + idx) = *(uint4*)hb;
    *(uint4*)(olo + idx) = *(uint4*)lb;
}

// ---------------- pooling / head ----------------
__global__ __launch_bounds__(128) void k_pool(
    const float* __restrict__ h, const float* __restrict__ gamma,
    const float* __restrict__ beta)
{
    int g = blockIdx.x;
    int c = blockIdx.y * 128 + threadIdx.x;
    int s0 = g_gstart[g], s1 = g_gend[g];
    float sum = 0.f;
    for (int i = s0; i < s1; i++) sum += h[(size_t)i * HF + c];
    float cnt = (float)((s1 - s0) > 1 ? (s1 - s0) : 1);
    float v = sum / cnt;
    v = v * rsqrtf(1.f + 1e-5f) * gamma[c] + beta[c];
    g_hg[g * HF + c] = v;
}

__global__ __launch_bounds__(512) void k_fc1(
    const float* __restrict__ W, const float* __restrict__ b)
{
    int g = blockIdx.x;
    int c = threadIdx.x;
    __shared__ float x[HF];
    x[c] = g_hg[g * HF + c];
    __syncthreads();
    float acc = b[c];
    for (int k = 0; k < HF; k++) acc += x[k] * W[k * HF + c];
    g_hg2[g * HF + c] = acc > 0.f ? acc : expm1f(acc);
}

__global__ void k_final(const float* __restrict__ Wf, const float* __restrict__ bf,
                        float* __restrict__ out)
{
    int t = threadIdx.x;          // 128 = 64 graphs * 2 classes
    int g = t >> 1, c = t & 1;
    float acc = bf[c];
    const float* x = g_hg2 + g * HF;
    for (int k = 0; k < HF; k++) acc += x[k] * Wf[k * 2 + c];
    out[g * 2 + c] = acc;
}

// ---------------- host orchestration ----------------
static void gat_layer(const float* feat, const float* al, const float* ar,
                      const float* b, const int* src,
                      __nv_bfloat16* ohi, __nv_bfloat16* olo)
{
    k_elr<<<NN, 128>>>(feat, al, ar);
    k_attn<<<(NN + 7) / 8, 256>>>(src);
    k_aggregate<<<NN, 256>>>(feat, src, b, ohi, olo);
}

static void run_gemm(const __nv_bfloat16* ah, const __nv_bfloat16* al,
                     const __nv_bfloat16* wth, const __nv_bfloat16* wtl,
                     const float* bias,
                     float* C, __nv_bfloat16* Chi, __nv_bfloat16* Clo,
                     int M, int N, int K, int act)
{
    tc_gemm<<<dim3(N / 128, (M + 127) / 128), 256, TC_SMEM>>>(
        ah, al, wth, wtl, bias, C, Chi, Clo, M, N, K, act);
}

static void run_gemm_s(const __nv_bfloat16* ah, const __nv_bfloat16* al,
                       const __nv_bfloat16* wth, const __nv_bfloat16* wtl,
                       const float* bias,
                       float* C, __nv_bfloat16* Chi, __nv_bfloat16* Clo,
                       int M, int N, int K, int act)
{
    tc_gemm_s<<<dim3(N / 128, (M + 63) / 64), 256, TC_SMEM_S>>>(
        ah, al, wth, wtl, bias, C, Chi, Clo, M, N, K, act);
}

extern "C" void kernel_launch(void* const* d_in, const int* in_sizes, int n_in,
                              void* d_out, int out_size)
{
    (void)in_sizes; (void)n_in; (void)out_size;
    const float* node_feat = (const float*)d_in[0];
    // d_in[1] = func_feat  : dead for output, skipped
    const float* W1   = (const float*)d_in[2];
    const float* al1  = (const float*)d_in[3];
    const float* ar1  = (const float*)d_in[4];
    const float* b1   = (const float*)d_in[5];
    const float* W2   = (const float*)d_in[6];
    const float* al2  = (const float*)d_in[7];
    const float* ar2  = (const float*)d_in[8];
    const float* b2   = (const float*)d_in[9];
    const float* Wfc  = (const float*)d_in[10];
    const float* bfc  = (const float*)d_in[11];
    // d_in[12] = Wfco, d_in[13] = bfco : dead for output, skipped
    const float* Wh   = (const float*)d_in[14];
    const float* bh   = (const float*)d_in[15];
    const float* gamma= (const float*)d_in[16];
    const float* beta = (const float*)d_in[17];
    const float* Whfc = (const float*)d_in[18];
    const float* bhfc = (const float*)d_in[19];
    const float* Wf   = (const float*)d_in[20];
    const float* bf   = (const float*)d_in[21];
    const int* src    = (const int*)d_in[22];
    const int* dst    = (const int*)d_in[23];
    const int* gid    = (const int*)d_in[24];

    float *feat, *h0;
    __nv_bfloat16 *ah, *al, *bhp, *blp, *wth, *wtl;
    cudaGetSymbolAddress((void**)&feat, g_feat);
    cudaGetSymbolAddress((void**)&h0,   g_h0);
    cudaGetSymbolAddress((void**)&ah,   g_ah);
    cudaGetSymbolAddress((void**)&al,   g_al);
    cudaGetSymbolAddress((void**)&bhp,  g_bh);
    cudaGetSymbolAddress((void**)&blp,  g_bl);
    cudaGetSymbolAddress((void**)&wth,  g_wth);
    cudaGetSymbolAddress((void**)&wtl,  g_wtl);

    cudaFuncSetAttribute(tc_gemm, cudaFuncAttributeMaxDynamicSharedMemorySize,
                         TC_SMEM);
    cudaFuncSetAttribute(tc_gemm_s, cudaFuncAttributeMaxDynamicSharedMemorySize,
                         TC_SMEM_S);

    // ---- launch order chosen so tc_gemm is the 4th launch (ncu capture slot) ----
    // 1: W1 split   2: node_feat split   3: csr_init   4: tc_gemm (GEMM1)
    k_wsplit<<<dim3(2048 / 32, 768 / 32), dim3(32, 8)>>>(W1, wth + OFF_W1, wtl + OFF_W1, 768, 2048);
    k_split<<<4096, 256>>>(node_feat, ah, al, NN * EMB);
    k_csr_init<<<(NN + 255) / 256, 256>>>();
    run_gemm(ah, al, wth + OFF_W1, wtl + OFF_W1, nullptr,
             feat, nullptr, nullptr, NN, HD, EMB, 0);

    // ---- remaining graph preprocessing (must precede k_attn) ----
    k_degree<<<(NE + 255) / 256, 256>>>(dst);
    k_scan<<<1, 1024>>>();
    k_csr_fill<<<(NE + 255) / 256, 256>>>(dst);
    k_bounds<<<(NN + 255) / 256, 256>>>(gid);

    // ---- remaining weight splits ----
    k_wsplit<<<dim3(2048 / 32, 2048 / 32), dim3(32, 8)>>>(W2, wth + OFF_W2, wtl + OFF_W2, 2048, 2048);
    k_wsplit<<<dim3(512 / 32, 2048 / 32), dim3(32, 8)>>>(Wfc, wth + OFF_WFC, wtl + OFF_WFC, 2048, 512);
    for (int i = 0; i < 8; i++)
        k_wsplit<<<dim3(512 / 32, 512 / 32), dim3(32, 8)>>>(
            Wh + (size_t)i * HF * HF, wth + OFF_WH + (size_t)i * WH_SZ,
            wtl + OFF_WH + (size_t)i * WH_SZ, 512, 512);

    // ---- GAT layer 1 attention + aggregation ----
    gat_layer(feat, al1, ar1, b1, src, bhp, blp);   // -> bf16 pair

    // ---- GAT layer 2 ----
    run_gemm(bhp, blp, wth + OFF_W2, wtl + OFF_W2, nullptr,
             feat, nullptr, nullptr, NN, HD, HD, 0);
    gat_layer(feat, al2, ar2, b2, src, bhp, blp);   // -> bf16 pair

    // ---- h = elu(gat @ Wfc + bfc) -> bf16 pair (small-tile kernel, N=512) ----
    run_gemm_s(bhp, blp, wth + OFF_WFC, wtl + OFF_WFC, bfc,
               nullptr, ah, al, NN, HF, HD, 1);

    // ---- 8 hidden layers (h branch only; h_func is dead) ----
    __nv_bfloat16 *cih = ah, *cil = al, *coh = bhp, *col = blp;
    for (int i = 0; i < 7; i++) {
        run_gemm_s(cih, cil, wth + OFF_WH + (size_t)i * WH_SZ,
                   wtl + OFF_WH + (size_t)i * WH_SZ, bh + i * HF,
                   nullptr, coh, col, NN, HF, HF, 1);
        __nv_bfloat16* t;
        t = cih; cih = coh; coh = t;
        t = cil; cil = col; col = t;
    }
    run_gemm_s(cih, cil, wth + OFF_WH + (size_t)7 * WH_SZ,
               wtl + OFF_WH + (size_t)7 * WH_SZ, bh + 7 * HF,
               h0, nullptr, nullptr, NN, HF, HF, 1);

    // ---- mean-pool per graph + BatchNorm (eval) folded ----
    k_pool<<<dim3(NG, 4), 128>>>(h0, gamma, beta);
    k_fc1<<<NG, 512>>>(Whfc, bhfc);
    k_final<<<1, 128>>>(Wf, bf, (float*)d_out);
}